// round 2
// baseline (speedup 1.0000x reference)
#include <cuda_runtime.h>
#include <math.h>

#define BATCH 8
#define NN 2048
#define DD 768

// Scratch (device globals: allocation-free rule)
__device__ float g_midn[(size_t)BATCH * NN * DD];          // normalized mid features
__device__ float g_sim[(size_t)BATCH * NN * NN];           // sim, then exp(sim - max)
__device__ float g_conf[BATCH * NN];                       // row max (confidence)
__device__ float g_rinv[BATCH * NN];                       // 1 / row sum of exp

// ---------------------------------------------------------------------------
// Kernel 1: L2-normalize mid features along D. One block per (b, n) row.
// ---------------------------------------------------------------------------
__global__ void norm_kernel(const float* __restrict__ mid) {
    const int row = blockIdx.x;                 // 0 .. BATCH*NN-1
    const float* x = mid + (size_t)row * DD;
    float* y = g_midn + (size_t)row * DD;

    float s = 0.f;
    for (int i = threadIdx.x; i < DD; i += blockDim.x) {
        float v = x[i];
        s += v * v;
    }
    // block reduce sum
    __shared__ float sh[32];
    #pragma unroll
    for (int o = 16; o > 0; o >>= 1) s += __shfl_xor_sync(0xffffffffu, s, o);
    const int w = threadIdx.x >> 5, l = threadIdx.x & 31;
    if (l == 0) sh[w] = s;
    __syncthreads();
    if (w == 0) {
        float v = (threadIdx.x < (blockDim.x >> 5)) ? sh[threadIdx.x] : 0.f;
        #pragma unroll
        for (int o = 16; o > 0; o >>= 1) v += __shfl_xor_sync(0xffffffffu, v, o);
        if (threadIdx.x == 0) sh[0] = v;
    }
    __syncthreads();
    const float inv = 1.0f / fmaxf(sqrtf(sh[0]), 1e-12f);

    for (int i = threadIdx.x; i < DD; i += blockDim.x) y[i] = x[i] * inv;
}

// ---------------------------------------------------------------------------
// Kernel 2: sim = midn @ midn^T (symmetric). Upper-triangle tiles only;
// mirror write for off-diagonal tiles; zero the diagonal in-place.
// 64x64 tile, BK=16, 16x16 threads, 4x4 microtile.
// ---------------------------------------------------------------------------
#define TBM 64
#define TBK 16

__global__ void sim_kernel() {
    const int bj = blockIdx.x;      // column tile
    const int bi = blockIdx.y;      // row tile
    if (bi > bj) return;            // symmetry: upper triangle only
    const int b = blockIdx.z;

    __shared__ float As[TBK][TBM];
    __shared__ float Bs[TBK][TBM];

    const float* Abase = g_midn + (size_t)b * NN * DD;
    float* simb = g_sim + (size_t)b * NN * NN;

    const int tx = threadIdx.x, ty = threadIdx.y;
    const int tid = ty * 16 + tx;

    // load mapping: thread t loads one float4 per tile: row = t/4, kq = t%4
    const int lm = tid >> 2;        // 0..63 (row within tile)
    const int lk = (tid & 3) * 4;   // 0,4,8,12 (k offset)

    float acc[4][4];
    #pragma unroll
    for (int i = 0; i < 4; i++)
        #pragma unroll
        for (int j = 0; j < 4; j++) acc[i][j] = 0.f;

    const int row0 = bi * TBM;
    const int col0 = bj * TBM;

    for (int kt = 0; kt < DD; kt += TBK) {
        float4 av = *(const float4*)(Abase + (size_t)(row0 + lm) * DD + kt + lk);
        float4 bv = *(const float4*)(Abase + (size_t)(col0 + lm) * DD + kt + lk);
        As[lk + 0][lm] = av.x; As[lk + 1][lm] = av.y;
        As[lk + 2][lm] = av.z; As[lk + 3][lm] = av.w;
        Bs[lk + 0][lm] = bv.x; Bs[lk + 1][lm] = bv.y;
        Bs[lk + 2][lm] = bv.z; Bs[lk + 3][lm] = bv.w;
        __syncthreads();

        #pragma unroll
        for (int k = 0; k < TBK; k++) {
            float4 a = *(const float4*)&As[k][ty * 4];
            float4 bb = *(const float4*)&Bs[k][tx * 4];
            float ar[4] = {a.x, a.y, a.z, a.w};
            float br[4] = {bb.x, bb.y, bb.z, bb.w};
            #pragma unroll
            for (int i = 0; i < 4; i++)
                #pragma unroll
                for (int j = 0; j < 4; j++) acc[i][j] += ar[i] * br[j];
        }
        __syncthreads();
    }

    const int r0 = row0 + ty * 4;
    const int c0 = col0 + tx * 4;
    const bool diag_tile = (bi == bj);
    #pragma unroll
    for (int i = 0; i < 4; i++) {
        #pragma unroll
        for (int j = 0; j < 4; j++) {
            const int r = r0 + i, c = c0 + j;
            float v = acc[i][j];
            if (r == c) v = 0.f;                     // zero diagonal
            simb[(size_t)r * NN + c] = v;
            if (!diag_tile) simb[(size_t)c * NN + r] = v;   // mirror
        }
    }
}

// ---------------------------------------------------------------------------
// Kernel 3: per-row: confidence = max(sim_row) (diag already 0);
// sim_row <- exp(sim_row - max); store 1/sum. One block per row.
// ---------------------------------------------------------------------------
__global__ void softmax_kernel() {
    const int row = blockIdx.x;                 // 0 .. BATCH*NN-1
    const int b = row / NN;
    const int r = row - b * NN;
    float* srow = g_sim + (size_t)b * NN * NN + (size_t)r * NN;

    __shared__ float sh[32];

    // pass 1: max
    float m = -INFINITY;
    for (int i = threadIdx.x; i < NN; i += blockDim.x) m = fmaxf(m, srow[i]);
    #pragma unroll
    for (int o = 16; o > 0; o >>= 1) m = fmaxf(m, __shfl_xor_sync(0xffffffffu, m, o));
    const int w = threadIdx.x >> 5, l = threadIdx.x & 31;
    if (l == 0) sh[w] = m;
    __syncthreads();
    if (w == 0) {
        float v = (threadIdx.x < (blockDim.x >> 5)) ? sh[threadIdx.x] : -INFINITY;
        #pragma unroll
        for (int o = 16; o > 0; o >>= 1) v = fmaxf(v, __shfl_xor_sync(0xffffffffu, v, o));
        if (threadIdx.x == 0) sh[0] = v;
    }
    __syncthreads();
    m = sh[0];
    __syncthreads();

    // pass 2: exp + sum
    float s = 0.f;
    for (int i = threadIdx.x; i < NN; i += blockDim.x) {
        float e = __expf(srow[i] - m);
        srow[i] = e;
        s += e;
    }
    #pragma unroll
    for (int o = 16; o > 0; o >>= 1) s += __shfl_xor_sync(0xffffffffu, s, o);
    if (l == 0) sh[w] = s;
    __syncthreads();
    if (w == 0) {
        float v = (threadIdx.x < (blockDim.x >> 5)) ? sh[threadIdx.x] : 0.f;
        #pragma unroll
        for (int o = 16; o > 0; o >>= 1) v += __shfl_xor_sync(0xffffffffu, v, o);
        if (threadIdx.x == 0) {
            g_conf[row] = m;
            g_rinv[row] = 1.0f / v;
        }
    }
}

// ---------------------------------------------------------------------------
// Kernel 4: out = cw * (E @ final) * rinv + (1-cw) * final
// E = exp matrix [NN x NN], final [NN x DD]. 64x64 tile over (n, d), K = NN.
// ---------------------------------------------------------------------------
__global__ void out_kernel(const float* __restrict__ fin, float* __restrict__ out) {
    const int bx = blockIdx.x;      // d tile (DD/64 = 12)
    const int by = blockIdx.y;      // n tile (NN/64 = 32)
    const int b = blockIdx.z;

    __shared__ float As[TBK][TBM];
    __shared__ float Bs[TBK][TBM];

    const float* E = g_sim + (size_t)b * NN * NN;
    const float* F = fin + (size_t)b * NN * DD;

    const int tx = threadIdx.x, ty = threadIdx.y;
    const int tid = ty * 16 + tx;

    const int row0 = by * TBM;      // output n rows
    const int col0 = bx * TBM;      // output d cols

    // A (E) loads: row = tid/4, k offset = (tid%4)*4
    const int lam = tid >> 2;
    const int lak = (tid & 3) * 4;
    // B (F) loads: k row = tid/16, n offset = (tid%16)*4
    const int lbk = tid >> 4;
    const int lbn = (tid & 15) * 4;

    float acc[4][4];
    #pragma unroll
    for (int i = 0; i < 4; i++)
        #pragma unroll
        for (int j = 0; j < 4; j++) acc[i][j] = 0.f;

    for (int kt = 0; kt < NN; kt += TBK) {
        float4 av = *(const float4*)(E + (size_t)(row0 + lam) * NN + kt + lak);
        As[lak + 0][lam] = av.x; As[lak + 1][lam] = av.y;
        As[lak + 2][lam] = av.z; As[lak + 3][lam] = av.w;
        float4 bv = *(const float4*)(F + (size_t)(kt + lbk) * DD + col0 + lbn);
        *(float4*)&Bs[lbk][lbn] = bv;
        __syncthreads();

        #pragma unroll
        for (int k = 0; k < TBK; k++) {
            float4 a = *(const float4*)&As[k][ty * 4];
            float4 bb = *(const float4*)&Bs[k][tx * 4];
            float ar[4] = {a.x, a.y, a.z, a.w};
            float br[4] = {bb.x, bb.y, bb.z, bb.w};
            #pragma unroll
            for (int i = 0; i < 4; i++)
                #pragma unroll
                for (int j = 0; j < 4; j++) acc[i][j] += ar[i] * br[j];
        }
        __syncthreads();
    }

    float* O = out + (size_t)b * NN * DD;
    #pragma unroll
    for (int i = 0; i < 4; i++) {
        const int r = row0 + ty * 4 + i;
        const float cw = g_conf[b * NN + r];
        const float inv = g_rinv[b * NN + r];
        #pragma unroll
        for (int j = 0; j < 4; j++) {
            const int c = col0 + tx * 4 + j;
            const float f = F[(size_t)r * DD + c];
            O[(size_t)r * DD + c] = cw * (acc[i][j] * inv) + (1.0f - cw) * f;
        }
    }
}

// ---------------------------------------------------------------------------
extern "C" void kernel_launch(void* const* d_in, const int* in_sizes, int n_in,
                              void* d_out, int out_size) {
    const float* final_f = (const float*)d_in[0];
    const float* mid_f   = (const float*)d_in[1];
    float* out = (float*)d_out;

    norm_kernel<<<BATCH * NN, 256>>>(mid_f);

    dim3 tb(16, 16);
    dim3 g2(NN / TBM, NN / TBM, BATCH);
    sim_kernel<<<g2, tb>>>();

    softmax_kernel<<<BATCH * NN, 256>>>();

    dim3 g4(DD / TBM, NN / TBM, BATCH);
    out_kernel<<<g4, tb>>>(final_f, out);
}

// round 4
// speedup vs baseline: 3.4494x; 3.4494x over previous
#include <cuda_runtime.h>
#include <cuda_bf16.h>
#include <stdint.h>
#include <stddef.h>
#include <math.h>

#define BATCH 8
#define NN 2048
#define DD 768

// ---------------- device scratch (allocation-free rule) ----------------
__device__ __nv_bfloat16 g_midn[(size_t)BATCH * NN * DD];   // normalized mid (bf16)
__device__ __nv_bfloat16 g_finb[(size_t)BATCH * NN * DD];   // final (bf16)
__device__ float         g_sim [(size_t)BATCH * NN * NN];   // fp32 similarity
__device__ __nv_bfloat16 g_expb[(size_t)BATCH * NN * NN];   // bf16 exp(sim - max)
__device__ float         g_conf[BATCH * NN];                // row max (confidence)
__device__ float         g_rinv[BATCH * NN];                // 1 / row sum of exp

__device__ __forceinline__ uint32_t s2u(const void* p) {
    return (uint32_t)__cvta_generic_to_shared(p);
}

// swizzled index (in halves) for tiles with 32-half (64B) rows.
// kh is a multiple of 8 (16B chunk granularity).
__device__ __forceinline__ int swA(int row, int kh) {
    return (row << 5) | ((((kh >> 3) ^ ((row >> 1) & 3)) << 3));
}
// swizzled index for the F tile: 32 rows (k) x 128 halves (d) per row.
__device__ __forceinline__ int swF(int kr, int dh) {
    int c  = dh >> 3;                       // 0..15
    int cs = (c & 8) | ((c ^ (kr & 7)) & 7);
    return (kr << 7) | (cs << 3);
}

// ---------------------------------------------------------------------------
// Kernel 1: L2-normalize mid along D, emit bf16. One block per (b, n) row.
// ---------------------------------------------------------------------------
__global__ void norm_kernel(const float* __restrict__ mid) {
    const int row = blockIdx.x;
    const float* x = mid + (size_t)row * DD;
    __nv_bfloat16* y = g_midn + (size_t)row * DD;

    float s = 0.f;
    for (int i = threadIdx.x; i < DD; i += blockDim.x) {
        float v = x[i];
        s += v * v;
    }
    __shared__ float sh[32];
    #pragma unroll
    for (int o = 16; o > 0; o >>= 1) s += __shfl_xor_sync(0xffffffffu, s, o);
    const int w = threadIdx.x >> 5, l = threadIdx.x & 31;
    if (l == 0) sh[w] = s;
    __syncthreads();
    if (w == 0) {
        float v = (threadIdx.x < (blockDim.x >> 5)) ? sh[threadIdx.x] : 0.f;
        #pragma unroll
        for (int o = 16; o > 0; o >>= 1) v += __shfl_xor_sync(0xffffffffu, v, o);
        if (threadIdx.x == 0) sh[0] = v;
    }
    __syncthreads();
    const float inv = 1.0f / fmaxf(sqrtf(sh[0]), 1e-12f);
    for (int i = threadIdx.x; i < DD; i += blockDim.x)
        y[i] = __float2bfloat16(x[i] * inv);
}

// ---------------------------------------------------------------------------
// Kernel 1b: convert final features fp32 -> bf16.
// ---------------------------------------------------------------------------
__global__ void cvt_final(const float4* __restrict__ f) {
    const size_t i = (size_t)blockIdx.x * blockDim.x + threadIdx.x;
    const size_t n4 = (size_t)BATCH * NN * DD / 4;
    if (i >= n4) return;
    float4 v = f[i];
    __nv_bfloat162 lo, hi;
    lo.x = __float2bfloat16(v.x); lo.y = __float2bfloat16(v.y);
    hi.x = __float2bfloat16(v.z); hi.y = __float2bfloat16(v.w);
    ((__nv_bfloat162*)g_finb)[i * 2 + 0] = lo;
    ((__nv_bfloat162*)g_finb)[i * 2 + 1] = hi;
}

// ---------------------------------------------------------------------------
// Kernel 2: sim = midn @ midn^T, fp32 out, diagonal zeroed.
// 128x128x32 tiles, mma.sync.m16n8k16 bf16, 8 warps (4x2), warp tile 32x64.
// ---------------------------------------------------------------------------
__global__ __launch_bounds__(256) void sim_mma() {
    __shared__ __nv_bfloat16 As[128 * 32];
    __shared__ __nv_bfloat16 Bs[128 * 32];
    const int b = blockIdx.z;
    const int row0 = blockIdx.y << 7;
    const int col0 = blockIdx.x << 7;
    const __nv_bfloat16* Ab = g_midn + (size_t)b * NN * DD;

    const int tid = threadIdx.x, lane = tid & 31, wid = tid >> 5;
    const int wm = (wid >> 1) << 5;   // 0,32,64,96
    const int wn = (wid & 1) << 6;    // 0,64

    float acc[2][8][4];
    #pragma unroll
    for (int i = 0; i < 2; i++)
        #pragma unroll
        for (int j = 0; j < 8; j++)
            #pragma unroll
            for (int k = 0; k < 4; k++) acc[i][j][k] = 0.f;

    // gmem->smem mapping: 512 16B-chunks, 2 per thread
    const int r0q = tid & 127,          c0q = (tid >> 7) << 3;
    const int r1q = (tid + 256) & 127,  c1q = ((tid + 256) >> 7) << 3;

    for (int kt = 0; kt < DD; kt += 32) {
        uint4 av0 = *(const uint4*)(Ab + (size_t)(row0 + r0q) * DD + kt + c0q);
        uint4 av1 = *(const uint4*)(Ab + (size_t)(row0 + r1q) * DD + kt + c1q);
        uint4 bv0 = *(const uint4*)(Ab + (size_t)(col0 + r0q) * DD + kt + c0q);
        uint4 bv1 = *(const uint4*)(Ab + (size_t)(col0 + r1q) * DD + kt + c1q);
        __syncthreads();
        *(uint4*)&As[swA(r0q, c0q)] = av0;
        *(uint4*)&As[swA(r1q, c1q)] = av1;
        *(uint4*)&Bs[swA(r0q, c0q)] = bv0;
        *(uint4*)&Bs[swA(r1q, c1q)] = bv1;
        __syncthreads();

        #pragma unroll
        for (int ks = 0; ks < 2; ks++) {
            uint32_t af[2][4];
            #pragma unroll
            for (int i = 0; i < 2; i++) {
                int row = wm + i * 16 + (lane & 15);
                int kh  = ks * 16 + ((lane >> 4) << 3);
                uint32_t ad = s2u(&As[swA(row, kh)]);
                asm volatile("ldmatrix.sync.aligned.m8n8.x4.shared.b16 {%0,%1,%2,%3}, [%4];"
                    : "=r"(af[i][0]), "=r"(af[i][1]), "=r"(af[i][2]), "=r"(af[i][3])
                    : "r"(ad));
            }
            uint32_t bf[8][2];
            #pragma unroll
            for (int j2 = 0; j2 < 4; j2++) {
                int row = wn + j2 * 16 + (lane & 7) + (((lane >> 4) & 1) << 3);
                int kh  = ks * 16 + (((lane >> 3) & 1) << 3);
                uint32_t bd = s2u(&Bs[swA(row, kh)]);
                asm volatile("ldmatrix.sync.aligned.m8n8.x4.shared.b16 {%0,%1,%2,%3}, [%4];"
                    : "=r"(bf[j2 * 2][0]), "=r"(bf[j2 * 2][1]),
                      "=r"(bf[j2 * 2 + 1][0]), "=r"(bf[j2 * 2 + 1][1])
                    : "r"(bd));
            }
            #pragma unroll
            for (int i = 0; i < 2; i++)
                #pragma unroll
                for (int j = 0; j < 8; j++)
                    asm volatile(
                        "mma.sync.aligned.m16n8k16.row.col.f32.bf16.bf16.f32 "
                        "{%0,%1,%2,%3}, {%4,%5,%6,%7}, {%8,%9}, {%0,%1,%2,%3};"
                        : "+f"(acc[i][j][0]), "+f"(acc[i][j][1]),
                          "+f"(acc[i][j][2]), "+f"(acc[i][j][3])
                        : "r"(af[i][0]), "r"(af[i][1]), "r"(af[i][2]), "r"(af[i][3]),
                          "r"(bf[j][0]), "r"(bf[j][1]));
        }
    }

    float* simb = g_sim + (size_t)b * NN * NN;
    const int gr = lane >> 2, gc = (lane & 3) << 1;
    #pragma unroll
    for (int i = 0; i < 2; i++) {
        int r = row0 + wm + i * 16 + gr;
        #pragma unroll
        for (int j = 0; j < 8; j++) {
            int c = col0 + wn + j * 8 + gc;
            float2 v;
            v.x = (r == c)     ? 0.f : acc[i][j][0];
            v.y = (r == c + 1) ? 0.f : acc[i][j][1];
            *(float2*)(simb + (size_t)r * NN + c) = v;
            int r2 = r + 8;
            v.x = (r2 == c)     ? 0.f : acc[i][j][2];
            v.y = (r2 == c + 1) ? 0.f : acc[i][j][3];
            *(float2*)(simb + (size_t)r2 * NN + c) = v;
        }
    }
}

// ---------------------------------------------------------------------------
// Kernel 3: per-row max (confidence), exp to bf16, 1/sum. One block per row.
// ---------------------------------------------------------------------------
__global__ void softmax_kernel() {
    const int row = blockIdx.x;
    const int b = row / NN;
    const int r = row - b * NN;
    const float* srow = g_sim + (size_t)b * NN * NN + (size_t)r * NN;
    __nv_bfloat16* erow = g_expb + (size_t)b * NN * NN + (size_t)r * NN;

    __shared__ float sh[32];

    float m = -INFINITY;
    for (int i = threadIdx.x; i < NN; i += blockDim.x) m = fmaxf(m, srow[i]);
    #pragma unroll
    for (int o = 16; o > 0; o >>= 1) m = fmaxf(m, __shfl_xor_sync(0xffffffffu, m, o));
    const int w = threadIdx.x >> 5, l = threadIdx.x & 31;
    if (l == 0) sh[w] = m;
    __syncthreads();
    if (w == 0) {
        float v = (threadIdx.x < (blockDim.x >> 5)) ? sh[threadIdx.x] : -INFINITY;
        #pragma unroll
        for (int o = 16; o > 0; o >>= 1) v = fmaxf(v, __shfl_xor_sync(0xffffffffu, v, o));
        if (threadIdx.x == 0) sh[0] = v;
    }
    __syncthreads();
    m = sh[0];
    __syncthreads();

    float s = 0.f;
    for (int i = threadIdx.x; i < NN; i += blockDim.x) {
        float e = __expf(srow[i] - m);
        erow[i] = __float2bfloat16(e);
        s += e;
    }
    #pragma unroll
    for (int o = 16; o > 0; o >>= 1) s += __shfl_xor_sync(0xffffffffu, s, o);
    if (l == 0) sh[w] = s;
    __syncthreads();
    if (w == 0) {
        float v = (threadIdx.x < (blockDim.x >> 5)) ? sh[threadIdx.x] : 0.f;
        #pragma unroll
        for (int o = 16; o > 0; o >>= 1) v += __shfl_xor_sync(0xffffffffu, v, o);
        if (threadIdx.x == 0) {
            g_conf[row] = m;
            g_rinv[row] = 1.0f / v;
        }
    }
}

// ---------------------------------------------------------------------------
// Kernel 4: refined = (E @ F) * rinv ; out = cw*refined + (1-cw)*final.
// E [N x N] bf16 row-major, F [N x D] bf16 (k-major rows -> ldmatrix.trans).
// ---------------------------------------------------------------------------
__global__ __launch_bounds__(256) void out_mma(const float* __restrict__ fin,
                                               float* __restrict__ out) {
    __shared__ __nv_bfloat16 Es[128 * 32];
    __shared__ __nv_bfloat16 Fs[32 * 128];
    const int b = blockIdx.z;
    const int row0 = blockIdx.y << 7;   // n rows of output
    const int col0 = blockIdx.x << 7;   // d cols of output
    const __nv_bfloat16* Eb = g_expb + (size_t)b * NN * NN;
    const __nv_bfloat16* Fb = g_finb + (size_t)b * NN * DD;

    const int tid = threadIdx.x, lane = tid & 31, wid = tid >> 5;
    const int wm = (wid >> 1) << 5;
    const int wn = (wid & 1) << 6;

    float acc[2][8][4];
    #pragma unroll
    for (int i = 0; i < 2; i++)
        #pragma unroll
        for (int j = 0; j < 8; j++)
            #pragma unroll
            for (int k = 0; k < 4; k++) acc[i][j][k] = 0.f;

    const int er0 = tid & 127,         ec0 = (tid >> 7) << 3;
    const int er1 = (tid + 256) & 127, ec1 = ((tid + 256) >> 7) << 3;
    const int fk0 = tid >> 4,          fd0 = (tid & 15) << 3;
    const int fk1 = (tid + 256) >> 4,  fd1 = ((tid + 256) & 15) << 3;

    for (int kt = 0; kt < NN; kt += 32) {
        uint4 ev0 = *(const uint4*)(Eb + (size_t)(row0 + er0) * NN + kt + ec0);
        uint4 ev1 = *(const uint4*)(Eb + (size_t)(row0 + er1) * NN + kt + ec1);
        uint4 fv0 = *(const uint4*)(Fb + (size_t)(kt + fk0) * DD + col0 + fd0);
        uint4 fv1 = *(const uint4*)(Fb + (size_t)(kt + fk1) * DD + col0 + fd1);
        __syncthreads();
        *(uint4*)&Es[swA(er0, ec0)] = ev0;
        *(uint4*)&Es[swA(er1, ec1)] = ev1;
        *(uint4*)&Fs[swF(fk0, fd0)] = fv0;
        *(uint4*)&Fs[swF(fk1, fd1)] = fv1;
        __syncthreads();

        #pragma unroll
        for (int ks = 0; ks < 2; ks++) {
            uint32_t af[2][4];
            #pragma unroll
            for (int i = 0; i < 2; i++) {
                int row = wm + i * 16 + (lane & 15);
                int kh  = ks * 16 + ((lane >> 4) << 3);
                uint32_t ad = s2u(&Es[swA(row, kh)]);
                asm volatile("ldmatrix.sync.aligned.m8n8.x4.shared.b16 {%0,%1,%2,%3}, [%4];"
                    : "=r"(af[i][0]), "=r"(af[i][1]), "=r"(af[i][2]), "=r"(af[i][3])
                    : "r"(ad));
            }
            uint32_t bf[8][2];
            #pragma unroll
            for (int j2 = 0; j2 < 4; j2++) {
                int kr = ks * 16 + (lane & 7) + (((lane >> 3) & 1) << 3);
                int dh = wn + j2 * 16 + ((lane >> 4) << 3);
                uint32_t bd = s2u(&Fs[swF(kr, dh)]);
                asm volatile("ldmatrix.sync.aligned.m8n8.x4.trans.shared.b16 {%0,%1,%2,%3}, [%4];"
                    : "=r"(bf[j2 * 2][0]), "=r"(bf[j2 * 2][1]),
                      "=r"(bf[j2 * 2 + 1][0]), "=r"(bf[j2 * 2 + 1][1])
                    : "r"(bd));
            }
            #pragma unroll
            for (int i = 0; i < 2; i++)
                #pragma unroll
                for (int j = 0; j < 8; j++)
                    asm volatile(
                        "mma.sync.aligned.m16n8k16.row.col.f32.bf16.bf16.f32 "
                        "{%0,%1,%2,%3}, {%4,%5,%6,%7}, {%8,%9}, {%0,%1,%2,%3};"
                        : "+f"(acc[i][j][0]), "+f"(acc[i][j][1]),
                          "+f"(acc[i][j][2]), "+f"(acc[i][j][3])
                        : "r"(af[i][0]), "r"(af[i][1]), "r"(af[i][2]), "r"(af[i][3]),
                          "r"(bf[j][0]), "r"(bf[j][1]));
        }
    }

    const float* F32 = fin + (size_t)b * NN * DD;
    float* O = out + (size_t)b * NN * DD;
    const int gr = lane >> 2, gc = (lane & 3) << 1;
    #pragma unroll
    for (int i = 0; i < 2; i++) {
        #pragma unroll
        for (int half = 0; half < 2; half++) {
            int r = row0 + wm + i * 16 + gr + half * 8;
            const float cw  = g_conf[b * NN + r];
            const float inv = g_rinv[b * NN + r];
            #pragma unroll
            for (int j = 0; j < 8; j++) {
                int c = col0 + wn + j * 8 + gc;
                float2 f = *(const float2*)(F32 + (size_t)r * DD + c);
                float2 o;
                o.x = cw * (acc[i][j][half * 2 + 0] * inv) + (1.0f - cw) * f.x;
                o.y = cw * (acc[i][j][half * 2 + 1] * inv) + (1.0f - cw) * f.y;
                *(float2*)(O + (size_t)r * DD + c) = o;
            }
        }
    }
}

// ---------------------------------------------------------------------------
extern "C" void kernel_launch(void* const* d_in, const int* in_sizes, int n_in,
                              void* d_out, int out_size) {
    const float* final_f = (const float*)d_in[0];
    const float* mid_f   = (const float*)d_in[1];
    float* out = (float*)d_out;

    norm_kernel<<<BATCH * NN, 256>>>(mid_f);
    cvt_final<<<(int)(((size_t)BATCH * NN * DD / 4 + 255) / 256), 256>>>(
        (const float4*)final_f);

    sim_mma<<<dim3(NN / 128, NN / 128, BATCH), 256>>>();

    softmax_kernel<<<BATCH * NN, 256>>>();

    out_mma<<<dim3(DD / 128, NN / 128, BATCH), 256>>>(final_f, out);
}

// round 5
// speedup vs baseline: 3.6786x; 1.0665x over previous
#include <cuda_runtime.h>
#include <cuda_bf16.h>
#include <stdint.h>
#include <stddef.h>
#include <math.h>

#define BATCH 8
#define NN 2048
#define DD 768

// ---------------- device scratch (allocation-free rule) ----------------
__device__ __nv_bfloat16 g_midn[(size_t)BATCH * NN * DD];   // normalized mid (bf16)
__device__ __nv_bfloat16 g_finb[(size_t)BATCH * NN * DD];   // final (bf16)
__device__ float         g_sim [(size_t)BATCH * NN * NN];   // fp32 similarity
__device__ __nv_bfloat16 g_expb[(size_t)BATCH * NN * NN];   // bf16 exp(sim - max)
__device__ unsigned      g_confbits[BATCH * NN];            // ordered-uint row max
__device__ float         g_conf[BATCH * NN];                // row max (confidence)
__device__ float         g_rinv[BATCH * NN];                // 1 / row sum of exp

__device__ __forceinline__ uint32_t s2u(const void* p) {
    return (uint32_t)__cvta_generic_to_shared(p);
}
__device__ __forceinline__ void cpa16(void* dst, const void* src) {
    asm volatile("cp.async.cg.shared.global [%0], [%1], 16;"
                 :: "r"(s2u(dst)), "l"(src));
}
#define CP_COMMIT() asm volatile("cp.async.commit_group;")
#define CP_WAIT(n)  asm volatile("cp.async.wait_group %0;" :: "n"(n))

// monotonic float<->uint for atomicMax
__device__ __forceinline__ unsigned fenc(float x) {
    unsigned b = __float_as_uint(x);
    return (b & 0x80000000u) ? ~b : (b | 0x80000000u);
}
__device__ __forceinline__ float fdec(unsigned e) {
    unsigned b = (e & 0x80000000u) ? (e ^ 0x80000000u) : ~e;
    return __uint_as_float(b);
}

// swizzled index (in halves) for tiles with 32-half (64B) rows.
__device__ __forceinline__ int swA(int row, int kh) {
    return (row << 5) | ((((kh >> 3) ^ ((row >> 1) & 3)) << 3));
}
// swizzled index for the F tile: 32 rows (k) x 128 halves (d) per row.
__device__ __forceinline__ int swF(int kr, int dh) {
    int c  = dh >> 3;
    int cs = (c & 8) | ((c ^ (kr & 7)) & 7);
    return (kr << 7) | (cs << 3);
}

// ---------------------------------------------------------------------------
// Kernel 1: L2-normalize mid along D -> bf16; also reset g_confbits.
// ---------------------------------------------------------------------------
__global__ void norm_kernel(const float* __restrict__ mid) {
    const int row = blockIdx.x;
    if (threadIdx.x == 0) g_confbits[row] = fenc(-INFINITY);
    const float* x = mid + (size_t)row * DD;
    __nv_bfloat16* y = g_midn + (size_t)row * DD;

    float s = 0.f;
    for (int i = threadIdx.x; i < DD; i += blockDim.x) {
        float v = x[i];
        s += v * v;
    }
    __shared__ float sh[32];
    #pragma unroll
    for (int o = 16; o > 0; o >>= 1) s += __shfl_xor_sync(0xffffffffu, s, o);
    const int w = threadIdx.x >> 5, l = threadIdx.x & 31;
    if (l == 0) sh[w] = s;
    __syncthreads();
    if (w == 0) {
        float v = (threadIdx.x < (blockDim.x >> 5)) ? sh[threadIdx.x] : 0.f;
        #pragma unroll
        for (int o = 16; o > 0; o >>= 1) v += __shfl_xor_sync(0xffffffffu, v, o);
        if (threadIdx.x == 0) sh[0] = v;
    }
    __syncthreads();
    const float inv = 1.0f / fmaxf(sqrtf(sh[0]), 1e-12f);
    for (int i = threadIdx.x; i < DD; i += blockDim.x)
        y[i] = __float2bfloat16(x[i] * inv);
}

// ---------------------------------------------------------------------------
// Kernel 1b: convert final features fp32 -> bf16.
// ---------------------------------------------------------------------------
__global__ void cvt_final(const float4* __restrict__ f) {
    const size_t i = (size_t)blockIdx.x * blockDim.x + threadIdx.x;
    const size_t n4 = (size_t)BATCH * NN * DD / 4;
    if (i >= n4) return;
    float4 v = f[i];
    __nv_bfloat162 lo, hi;
    lo.x = __float2bfloat16(v.x); lo.y = __float2bfloat16(v.y);
    hi.x = __float2bfloat16(v.z); hi.y = __float2bfloat16(v.w);
    ((__nv_bfloat162*)g_finb)[i * 2 + 0] = lo;
    ((__nv_bfloat162*)g_finb)[i * 2 + 1] = hi;
}

// ---------------------------------------------------------------------------
// Kernel 2: sim = midn @ midn^T, fp32 out, diag zeroed, fused row-max atomics.
// 128x128x32 tiles, cp.async 2-stage pipeline, mma.sync m16n8k16 bf16.
// ---------------------------------------------------------------------------
#define KT_SIM (DD / 32)

__global__ __launch_bounds__(256) void sim_mma() {
    __shared__ __nv_bfloat16 As[2][128 * 32];
    __shared__ __nv_bfloat16 Bs[2][128 * 32];
    const int b = blockIdx.z;
    const int row0 = blockIdx.y << 7;
    const int col0 = blockIdx.x << 7;
    const __nv_bfloat16* Ab = g_midn + (size_t)b * NN * DD;

    const int tid = threadIdx.x, lane = tid & 31, wid = tid >> 5;
    const int wm = (wid >> 1) << 5;
    const int wn = (wid & 1) << 6;

    float acc[2][8][4];
    #pragma unroll
    for (int i = 0; i < 2; i++)
        #pragma unroll
        for (int j = 0; j < 8; j++)
            #pragma unroll
            for (int k = 0; k < 4; k++) acc[i][j][k] = 0.f;

    const int r0q = tid & 127,          c0q = (tid >> 7) << 3;
    const int r1q = (tid + 256) & 127,  c1q = ((tid + 256) >> 7) << 3;

    #define SIM_LOAD(kt, p)                                                      \
        do {                                                                     \
            cpa16(&As[p][swA(r0q, c0q)], Ab + (size_t)(row0 + r0q) * DD + (kt) + c0q); \
            cpa16(&As[p][swA(r1q, c1q)], Ab + (size_t)(row0 + r1q) * DD + (kt) + c1q); \
            cpa16(&Bs[p][swA(r0q, c0q)], Ab + (size_t)(col0 + r0q) * DD + (kt) + c0q); \
            cpa16(&Bs[p][swA(r1q, c1q)], Ab + (size_t)(col0 + r1q) * DD + (kt) + c1q); \
        } while (0)

    SIM_LOAD(0, 0);
    CP_COMMIT();

    for (int kti = 0; kti < KT_SIM; kti++) {
        const int p = kti & 1;
        if (kti + 1 < KT_SIM) {
            SIM_LOAD((kti + 1) * 32, p ^ 1);
            CP_COMMIT();
            CP_WAIT(1);
        } else {
            CP_WAIT(0);
        }
        __syncthreads();

        #pragma unroll
        for (int ks = 0; ks < 2; ks++) {
            uint32_t af[2][4];
            #pragma unroll
            for (int i = 0; i < 2; i++) {
                int row = wm + i * 16 + (lane & 15);
                int kh  = ks * 16 + ((lane >> 4) << 3);
                uint32_t ad = s2u(&As[p][swA(row, kh)]);
                asm volatile("ldmatrix.sync.aligned.m8n8.x4.shared.b16 {%0,%1,%2,%3}, [%4];"
                    : "=r"(af[i][0]), "=r"(af[i][1]), "=r"(af[i][2]), "=r"(af[i][3])
                    : "r"(ad));
            }
            uint32_t bf[8][2];
            #pragma unroll
            for (int j2 = 0; j2 < 4; j2++) {
                int row = wn + j2 * 16 + (lane & 7) + (((lane >> 4) & 1) << 3);
                int kh  = ks * 16 + (((lane >> 3) & 1) << 3);
                uint32_t bd = s2u(&Bs[p][swA(row, kh)]);
                asm volatile("ldmatrix.sync.aligned.m8n8.x4.shared.b16 {%0,%1,%2,%3}, [%4];"
                    : "=r"(bf[j2 * 2][0]), "=r"(bf[j2 * 2][1]),
                      "=r"(bf[j2 * 2 + 1][0]), "=r"(bf[j2 * 2 + 1][1])
                    : "r"(bd));
            }
            #pragma unroll
            for (int i = 0; i < 2; i++)
                #pragma unroll
                for (int j = 0; j < 8; j++)
                    asm volatile(
                        "mma.sync.aligned.m16n8k16.row.col.f32.bf16.bf16.f32 "
                        "{%0,%1,%2,%3}, {%4,%5,%6,%7}, {%8,%9}, {%0,%1,%2,%3};"
                        : "+f"(acc[i][j][0]), "+f"(acc[i][j][1]),
                          "+f"(acc[i][j][2]), "+f"(acc[i][j][3])
                        : "r"(af[i][0]), "r"(af[i][1]), "r"(af[i][2]), "r"(af[i][3]),
                          "r"(bf[j][0]), "r"(bf[j][1]));
        }
        __syncthreads();
    }

    float* simb = g_sim + (size_t)b * NN * NN;
    const int gr = lane >> 2, gc = (lane & 3) << 1;
    #pragma unroll
    for (int i = 0; i < 2; i++) {
        int r = row0 + wm + i * 16 + gr;
        int r2 = r + 8;
        float m0 = -INFINITY, m1 = -INFINITY;
        #pragma unroll
        for (int j = 0; j < 8; j++) {
            int c = col0 + wn + j * 8 + gc;
            float2 v;
            v.x = (r == c)     ? 0.f : acc[i][j][0];
            v.y = (r == c + 1) ? 0.f : acc[i][j][1];
            *(float2*)(simb + (size_t)r * NN + c) = v;
            m0 = fmaxf(m0, fmaxf(v.x, v.y));
            v.x = (r2 == c)     ? 0.f : acc[i][j][2];
            v.y = (r2 == c + 1) ? 0.f : acc[i][j][3];
            *(float2*)(simb + (size_t)r2 * NN + c) = v;
            m1 = fmaxf(m1, fmaxf(v.x, v.y));
        }
        // reduce across the 4 lanes of the quad (same row)
        m0 = fmaxf(m0, __shfl_xor_sync(0xffffffffu, m0, 1));
        m0 = fmaxf(m0, __shfl_xor_sync(0xffffffffu, m0, 2));
        m1 = fmaxf(m1, __shfl_xor_sync(0xffffffffu, m1, 1));
        m1 = fmaxf(m1, __shfl_xor_sync(0xffffffffu, m1, 2));
        if ((lane & 3) == 0) {
            atomicMax(&g_confbits[b * NN + r],  fenc(m0));
            atomicMax(&g_confbits[b * NN + r2], fenc(m1));
        }
    }
}

// ---------------------------------------------------------------------------
// Kernel 3: single pass: e = exp(sim - max) -> bf16, rinv, conf.
// ---------------------------------------------------------------------------
__global__ void softmax_kernel() {
    const int row = blockIdx.x;
    const int b = row / NN;
    const int r = row - b * NN;
    const float* srow = g_sim + (size_t)b * NN * NN + (size_t)r * NN;
    __nv_bfloat16* erow = g_expb + (size_t)b * NN * NN + (size_t)r * NN;

    __shared__ float sh[32];
    const float m = fdec(g_confbits[row]);

    float s = 0.f;
    for (int i = threadIdx.x; i < NN; i += blockDim.x) {
        float e = __expf(srow[i] - m);
        erow[i] = __float2bfloat16(e);
        s += e;
    }
    #pragma unroll
    for (int o = 16; o > 0; o >>= 1) s += __shfl_xor_sync(0xffffffffu, s, o);
    const int w = threadIdx.x >> 5, l = threadIdx.x & 31;
    if (l == 0) sh[w] = s;
    __syncthreads();
    if (w == 0) {
        float v = (threadIdx.x < (blockDim.x >> 5)) ? sh[threadIdx.x] : 0.f;
        #pragma unroll
        for (int o = 16; o > 0; o >>= 1) v += __shfl_xor_sync(0xffffffffu, v, o);
        if (threadIdx.x == 0) {
            g_conf[row] = m;
            g_rinv[row] = 1.0f / v;
        }
    }
}

// ---------------------------------------------------------------------------
// Kernel 4: refined = (E @ F) * rinv ; out = cw*refined + (1-cw)*final.
// cp.async 2-stage pipeline.
// ---------------------------------------------------------------------------
#define KT_OUT (NN / 32)

__global__ __launch_bounds__(256) void out_mma(const float* __restrict__ fin,
                                               float* __restrict__ out) {
    __shared__ __nv_bfloat16 Es[2][128 * 32];
    __shared__ __nv_bfloat16 Fs[2][32 * 128];
    const int b = blockIdx.z;
    const int row0 = blockIdx.y << 7;
    const int col0 = blockIdx.x << 7;
    const __nv_bfloat16* Eb = g_expb + (size_t)b * NN * NN;
    const __nv_bfloat16* Fb = g_finb + (size_t)b * NN * DD;

    const int tid = threadIdx.x, lane = tid & 31, wid = tid >> 5;
    const int wm = (wid >> 1) << 5;
    const int wn = (wid & 1) << 6;

    float acc[2][8][4];
    #pragma unroll
    for (int i = 0; i < 2; i++)
        #pragma unroll
        for (int j = 0; j < 8; j++)
            #pragma unroll
            for (int k = 0; k < 4; k++) acc[i][j][k] = 0.f;

    const int er0 = tid & 127,         ec0 = (tid >> 7) << 3;
    const int er1 = (tid + 256) & 127, ec1 = ((tid + 256) >> 7) << 3;
    const int fk0 = tid >> 4,          fd0 = (tid & 15) << 3;
    const int fk1 = (tid + 256) >> 4,  fd1 = ((tid + 256) & 15) << 3;

    #define OUT_LOAD(kt, p)                                                           \
        do {                                                                          \
            cpa16(&Es[p][swA(er0, ec0)], Eb + (size_t)(row0 + er0) * NN + (kt) + ec0); \
            cpa16(&Es[p][swA(er1, ec1)], Eb + (size_t)(row0 + er1) * NN + (kt) + ec1); \
            cpa16(&Fs[p][swF(fk0, fd0)], Fb + (size_t)((kt) + fk0) * DD + col0 + fd0); \
            cpa16(&Fs[p][swF(fk1, fd1)], Fb + (size_t)((kt) + fk1) * DD + col0 + fd1); \
        } while (0)

    OUT_LOAD(0, 0);
    CP_COMMIT();

    for (int kti = 0; kti < KT_OUT; kti++) {
        const int p = kti & 1;
        if (kti + 1 < KT_OUT) {
            OUT_LOAD((kti + 1) * 32, p ^ 1);
            CP_COMMIT();
            CP_WAIT(1);
        } else {
            CP_WAIT(0);
        }
        __syncthreads();

        #pragma unroll
        for (int ks = 0; ks < 2; ks++) {
            uint32_t af[2][4];
            #pragma unroll
            for (int i = 0; i < 2; i++) {
                int row = wm + i * 16 + (lane & 15);
                int kh  = ks * 16 + ((lane >> 4) << 3);
                uint32_t ad = s2u(&Es[p][swA(row, kh)]);
                asm volatile("ldmatrix.sync.aligned.m8n8.x4.shared.b16 {%0,%1,%2,%3}, [%4];"
                    : "=r"(af[i][0]), "=r"(af[i][1]), "=r"(af[i][2]), "=r"(af[i][3])
                    : "r"(ad));
            }
            uint32_t bf[8][2];
            #pragma unroll
            for (int j2 = 0; j2 < 4; j2++) {
                int kr = ks * 16 + (lane & 7) + (((lane >> 3) & 1) << 3);
                int dh = wn + j2 * 16 + ((lane >> 4) << 3);
                uint32_t bd = s2u(&Fs[p][swF(kr, dh)]);
                asm volatile("ldmatrix.sync.aligned.m8n8.x4.trans.shared.b16 {%0,%1,%2,%3}, [%4];"
                    : "=r"(bf[j2 * 2][0]), "=r"(bf[j2 * 2][1]),
                      "=r"(bf[j2 * 2 + 1][0]), "=r"(bf[j2 * 2 + 1][1])
                    : "r"(bd));
            }
            #pragma unroll
            for (int i = 0; i < 2; i++)
                #pragma unroll
                for (int j = 0; j < 8; j++)
                    asm volatile(
                        "mma.sync.aligned.m16n8k16.row.col.f32.bf16.bf16.f32 "
                        "{%0,%1,%2,%3}, {%4,%5,%6,%7}, {%8,%9}, {%0,%1,%2,%3};"
                        : "+f"(acc[i][j][0]), "+f"(acc[i][j][1]),
                          "+f"(acc[i][j][2]), "+f"(acc[i][j][3])
                        : "r"(af[i][0]), "r"(af[i][1]), "r"(af[i][2]), "r"(af[i][3]),
                          "r"(bf[j][0]), "r"(bf[j][1]));
        }
        __syncthreads();
    }

    const float* F32 = fin + (size_t)b * NN * DD;
    float* O = out + (size_t)b * NN * DD;
    const int gr = lane >> 2, gc = (lane & 3) << 1;
    #pragma unroll
    for (int i = 0; i < 2; i++) {
        #pragma unroll
        for (int half = 0; half < 2; half++) {
            int r = row0 + wm + i * 16 + gr + half * 8;
            const float cw  = g_conf[b * NN + r];
            const float inv = g_rinv[b * NN + r];
            #pragma unroll
            for (int j = 0; j < 8; j++) {
                int c = col0 + wn + j * 8 + gc;
                float2 f = *(const float2*)(F32 + (size_t)r * DD + c);
                float2 o;
                o.x = cw * (acc[i][j][half * 2 + 0] * inv) + (1.0f - cw) * f.x;
                o.y = cw * (acc[i][j][half * 2 + 1] * inv) + (1.0f - cw) * f.y;
                *(float2*)(O + (size_t)r * DD + c) = o;
            }
        }
    }
}

// ---------------------------------------------------------------------------
extern "C" void kernel_launch(void* const* d_in, const int* in_sizes, int n_in,
                              void* d_out, int out_size) {
    const float* final_f = (const float*)d_in[0];
    const float* mid_f   = (const float*)d_in[1];
    float* out = (float*)d_out;

    norm_kernel<<<BATCH * NN, 256>>>(mid_f);
    cvt_final<<<(int)(((size_t)BATCH * NN * DD / 4 + 255) / 256), 256>>>(
        (const float4*)final_f);

    sim_mma<<<dim3(NN / 128, NN / 128, BATCH), 256>>>();

    softmax_kernel<<<BATCH * NN, 256>>>();

    out_mma<<<dim3(DD / 128, NN / 128, BATCH), 256>>>(final_f, out);
}

// round 7
// speedup vs baseline: 4.4770x; 1.2170x over previous
#include <cuda_runtime.h>
#include <cuda_bf16.h>
#include <stdint.h>
#include <stddef.h>
#include <math.h>

#define BATCH 8
#define NN 2048
#define DD 768
#define NTILE 16                    // 2048 / 128
#define NPAIRS (NTILE * (NTILE + 1) / 2)   // 136 upper-triangle tiles

// ---------------- device scratch (allocation-free rule) ----------------
__device__ __nv_bfloat16 g_midn[(size_t)BATCH * NN * DD];   // normalized mid (bf16)
__device__ __nv_bfloat16 g_finb[(size_t)BATCH * NN * DD];   // final (bf16)
__device__ __nv_bfloat16 g_expb[(size_t)BATCH * NN * NN];   // bf16 exp(sim), diag -> 1
__device__ unsigned      g_confbits[BATCH * NN];            // ordered-uint row max
__device__ float         g_conf[BATCH * NN];                // row max (confidence)
__device__ float         g_rinv[BATCH * NN];                // 1 / row sum of exp

__device__ __forceinline__ uint32_t s2u(const void* p) {
    return (uint32_t)__cvta_generic_to_shared(p);
}
__device__ __forceinline__ void cpa16(void* dst, const void* src) {
    asm volatile("cp.async.cg.shared.global [%0], [%1], 16;"
                 :: "r"(s2u(dst)), "l"(src));
}
#define CP_COMMIT() asm volatile("cp.async.commit_group;")
#define CP_WAIT(n)  asm volatile("cp.async.wait_group %0;" :: "n"(n))

// monotonic float<->uint for atomicMax
__device__ __forceinline__ unsigned fenc(float x) {
    unsigned b = __float_as_uint(x);
    return (b & 0x80000000u) ? ~b : (b | 0x80000000u);
}
__device__ __forceinline__ float fdec(unsigned e) {
    unsigned b = (e & 0x80000000u) ? (e ^ 0x80000000u) : ~e;
    return __uint_as_float(b);
}
__device__ __forceinline__ uint32_t pk2(float a, float b2) {
    __nv_bfloat162 h;
    h.x = __float2bfloat16(a); h.y = __float2bfloat16(b2);
    return *(uint32_t*)&h;
}

// swizzled index (in halves) for tiles with 32-half (64B) rows.
__device__ __forceinline__ int swA(int row, int kh) {
    return (row << 5) | ((((kh >> 3) ^ ((row >> 1) & 3)) << 3));
}
// swizzled index for the F tile: 32 rows (k) x 128 halves (d) per row.
__device__ __forceinline__ int swF(int kr, int dh) {
    int c  = dh >> 3;
    int cs = (c & 8) | ((c ^ (kr & 7)) & 7);
    return (kr << 7) | (cs << 3);
}

// ---------------------------------------------------------------------------
// Kernel 1: L2-normalize mid along D -> bf16; reset g_confbits.
// ---------------------------------------------------------------------------
__global__ void norm_kernel(const float* __restrict__ mid) {
    const int row = blockIdx.x;
    if (threadIdx.x == 0) g_confbits[row] = fenc(-INFINITY);
    const float* x = mid + (size_t)row * DD;
    __nv_bfloat16* y = g_midn + (size_t)row * DD;

    float s = 0.f;
    for (int i = threadIdx.x; i < DD; i += blockDim.x) {
        float v = x[i];
        s += v * v;
    }
    __shared__ float sh[32];
    #pragma unroll
    for (int o = 16; o > 0; o >>= 1) s += __shfl_xor_sync(0xffffffffu, s, o);
    const int w = threadIdx.x >> 5, l = threadIdx.x & 31;
    if (l == 0) sh[w] = s;
    __syncthreads();
    if (w == 0) {
        float v = (threadIdx.x < (blockDim.x >> 5)) ? sh[threadIdx.x] : 0.f;
        #pragma unroll
        for (int o = 16; o > 0; o >>= 1) v += __shfl_xor_sync(0xffffffffu, v, o);
        if (threadIdx.x == 0) sh[0] = v;
    }
    __syncthreads();
    const float inv = 1.0f / fmaxf(sqrtf(sh[0]), 1e-12f);
    for (int i = threadIdx.x; i < DD; i += blockDim.x)
        y[i] = __float2bfloat16(x[i] * inv);
}

// ---------------------------------------------------------------------------
// Kernel 1b: convert final features fp32 -> bf16.
// ---------------------------------------------------------------------------
__global__ void cvt_final(const float4* __restrict__ f) {
    const size_t i = (size_t)blockIdx.x * blockDim.x + threadIdx.x;
    const size_t n4 = (size_t)BATCH * NN * DD / 4;
    if (i >= n4) return;
    float4 v = f[i];
    ((uint32_t*)g_finb)[i * 2 + 0] = pk2(v.x, v.y);
    ((uint32_t*)g_finb)[i * 2 + 1] = pk2(v.z, v.w);
}

// ---------------------------------------------------------------------------
// Kernel 2: sim GEMM (upper-triangle tiles only) -> exp(sim) bf16 + row maxes.
// 128x128x32 mma.sync tiles, cp.async 2-stage pipeline, SMEM-staged epilogue
// that writes both the tile and (off-diag) its transpose.
// ---------------------------------------------------------------------------
#define KT_SIM (DD / 32)
#define STG 4096                                  // halves per stage buffer
#define SIM_SMEM (128 * 129 * 4)                  // 66048 B (>= 4*STG*2 = 32768)

__global__ __launch_bounds__(256) void sim_mma() {
    extern __shared__ char dsm[];
    __nv_bfloat16* As = (__nv_bfloat16*)dsm;       // [2][STG]
    __nv_bfloat16* Bs = As + 2 * STG;              // [2][STG]
    float* T = (float*)dsm;                        // [128][129] (reused after loop)

    // map linear tile id -> (bi, bj), bi <= bj
    int t = blockIdx.x, bi = 0, rem = NTILE;
    while (t >= rem) { t -= rem; rem--; bi++; }
    const int bj = bi + t;
    const int b = blockIdx.z;
    const int row0 = bi << 7, col0 = bj << 7;
    const bool diag = (bi == bj);
    const __nv_bfloat16* Ab = g_midn + (size_t)b * NN * DD;

    const int tid = threadIdx.x, lane = tid & 31, wid = tid >> 5;
    const int wm = (wid >> 1) << 5;
    const int wn = (wid & 1) << 6;

    float acc[2][8][4];
    #pragma unroll
    for (int i = 0; i < 2; i++)
        #pragma unroll
        for (int j = 0; j < 8; j++)
            #pragma unroll
            for (int k = 0; k < 4; k++) acc[i][j][k] = 0.f;

    const int r0q = tid & 127,          c0q = (tid >> 7) << 3;
    const int r1q = (tid + 256) & 127,  c1q = ((tid + 256) >> 7) << 3;

    #define SIM_LOAD(kt, p)                                                           \
        do {                                                                          \
            cpa16(&As[(p) * STG + swA(r0q, c0q)], Ab + (size_t)(row0 + r0q) * DD + (kt) + c0q); \
            cpa16(&As[(p) * STG + swA(r1q, c1q)], Ab + (size_t)(row0 + r1q) * DD + (kt) + c1q); \
            cpa16(&Bs[(p) * STG + swA(r0q, c0q)], Ab + (size_t)(col0 + r0q) * DD + (kt) + c0q); \
            cpa16(&Bs[(p) * STG + swA(r1q, c1q)], Ab + (size_t)(col0 + r1q) * DD + (kt) + c1q); \
        } while (0)

    SIM_LOAD(0, 0);
    CP_COMMIT();

    for (int kti = 0; kti < KT_SIM; kti++) {
        const int p = kti & 1;
        if (kti + 1 < KT_SIM) {
            SIM_LOAD((kti + 1) * 32, p ^ 1);
            CP_COMMIT();
            CP_WAIT(1);
        } else {
            CP_WAIT(0);
        }
        __syncthreads();

        #pragma unroll
        for (int ks = 0; ks < 2; ks++) {
            uint32_t af[2][4];
            #pragma unroll
            for (int i = 0; i < 2; i++) {
                int row = wm + i * 16 + (lane & 15);
                int kh  = ks * 16 + ((lane >> 4) << 3);
                uint32_t ad = s2u(&As[p * STG + swA(row, kh)]);
                asm volatile("ldmatrix.sync.aligned.m8n8.x4.shared.b16 {%0,%1,%2,%3}, [%4];"
                    : "=r"(af[i][0]), "=r"(af[i][1]), "=r"(af[i][2]), "=r"(af[i][3])
                    : "r"(ad));
            }
            uint32_t bf[8][2];
            #pragma unroll
            for (int j2 = 0; j2 < 4; j2++) {
                int row = wn + j2 * 16 + (lane & 7) + (((lane >> 4) & 1) << 3);
                int kh  = ks * 16 + (((lane >> 3) & 1) << 3);
                uint32_t bd = s2u(&Bs[p * STG + swA(row, kh)]);
                asm volatile("ldmatrix.sync.aligned.m8n8.x4.shared.b16 {%0,%1,%2,%3}, [%4];"
                    : "=r"(bf[j2 * 2][0]), "=r"(bf[j2 * 2][1]),
                      "=r"(bf[j2 * 2 + 1][0]), "=r"(bf[j2 * 2 + 1][1])
                    : "r"(bd));
            }
            #pragma unroll
            for (int i = 0; i < 2; i++)
                #pragma unroll
                for (int j = 0; j < 8; j++)
                    asm volatile(
                        "mma.sync.aligned.m16n8k16.row.col.f32.bf16.bf16.f32 "
                        "{%0,%1,%2,%3}, {%4,%5,%6,%7}, {%8,%9}, {%0,%1,%2,%3};"
                        : "+f"(acc[i][j][0]), "+f"(acc[i][j][1]),
                          "+f"(acc[i][j][2]), "+f"(acc[i][j][3])
                        : "r"(af[i][0]), "r"(af[i][1]), "r"(af[i][2]), "r"(af[i][3]),
                          "r"(bf[j][0]), "r"(bf[j][1]));
        }
        __syncthreads();
    }

    // ---- stage fp32 tile (diag zeroed) in SMEM ----
    const int gr = lane >> 2, gc = (lane & 3) << 1;
    #pragma unroll
    for (int i = 0; i < 2; i++) {
        const int rl = wm + i * 16 + gr;
        #pragma unroll
        for (int j = 0; j < 8; j++) {
            const int cl = wn + j * 8 + gc;
            const int gofs = (row0 + rl) - (col0 + cl);   // 0 when on diagonal
            T[rl * 129 + cl]           = (gofs == 0)  ? 0.f : acc[i][j][0];
            T[rl * 129 + cl + 1]       = (gofs == 1)  ? 0.f : acc[i][j][1];
            T[(rl + 8) * 129 + cl]     = (gofs == -8) ? 0.f : acc[i][j][2];
            T[(rl + 8) * 129 + cl + 1] = (gofs == -7) ? 0.f : acc[i][j][3];
        }
    }
    __syncthreads();

    // ---- row pass: write exp(tile) + row-max atomics ----
    {
        const int rr = tid >> 1, cs = (tid & 1) << 6;
        float mx = -INFINITY;
        uint32_t* dst = (uint32_t*)(g_expb + (size_t)b * NN * NN
                                    + (size_t)(row0 + rr) * NN + col0 + cs);
        #pragma unroll
        for (int c = 0; c < 64; c += 2) {
            float v0 = T[rr * 129 + cs + c];
            float v1 = T[rr * 129 + cs + c + 1];
            mx = fmaxf(mx, fmaxf(v0, v1));
            dst[c >> 1] = pk2(__expf(v0), __expf(v1));
        }
        atomicMax(&g_confbits[b * NN + row0 + rr], fenc(mx));
    }

    // ---- col pass (mirror) for off-diagonal tiles ----
    if (!diag) {
        const int cc = tid >> 1, rs = (tid & 1) << 6;
        float mx = -INFINITY;
        uint32_t* dst = (uint32_t*)(g_expb + (size_t)b * NN * NN
                                    + (size_t)(col0 + cc) * NN + row0 + rs);
        #pragma unroll
        for (int r = 0; r < 64; r += 2) {
            float v0 = T[(rs + r) * 129 + cc];
            float v1 = T[(rs + r + 1) * 129 + cc];
            mx = fmaxf(mx, fmaxf(v0, v1));
            dst[r >> 1] = pk2(__expf(v0), __expf(v1));
        }
        atomicMax(&g_confbits[b * NN + col0 + cc], fenc(mx));
    }
}

// ---------------------------------------------------------------------------
// Kernel 3: deterministic row sums of exp (bf16) -> rinv; conf from confbits.
// ---------------------------------------------------------------------------
__global__ void rowsum_kernel() {
    const int row = blockIdx.x;                  // 0 .. BATCH*NN-1
    const uint4* p = (const uint4*)(g_expb + (size_t)row * NN) + threadIdx.x * 2;
    float s = 0.f;
    #pragma unroll
    for (int q = 0; q < 2; q++) {
        uint4 v = p[q];
        const uint32_t w4[4] = {v.x, v.y, v.z, v.w};
        #pragma unroll
        for (int h = 0; h < 4; h++) {
            __nv_bfloat162 bb = *(const __nv_bfloat162*)&w4[h];
            float2 f = __bfloat1622float2(bb);
            s += f.x + f.y;
        }
    }
    __shared__ float sh[4];
    #pragma unroll
    for (int o = 16; o > 0; o >>= 1) s += __shfl_xor_sync(0xffffffffu, s, o);
    const int w = threadIdx.x >> 5, l = threadIdx.x & 31;
    if (l == 0) sh[w] = s;
    __syncthreads();
    if (threadIdx.x == 0) {
        float v = sh[0] + sh[1] + sh[2] + sh[3];
        g_conf[row] = fdec(g_confbits[row]);
        g_rinv[row] = 1.0f / v;
    }
}

// ---------------------------------------------------------------------------
// Kernel 4: refined = (E @ F) * rinv ; out = cw*refined + (1-cw)*final.
// (verified R5 kernel, unchanged)
// ---------------------------------------------------------------------------
#define KT_OUT (NN / 32)

__global__ __launch_bounds__(256) void out_mma(const float* __restrict__ fin,
                                               float* __restrict__ out) {
    __shared__ __nv_bfloat16 Es[2][128 * 32];
    __shared__ __nv_bfloat16 Fs[2][32 * 128];
    const int b = blockIdx.z;
    const int row0 = blockIdx.y << 7;
    const int col0 = blockIdx.x << 7;
    const __nv_bfloat16* Eb = g_expb + (size_t)b * NN * NN;
    const __nv_bfloat16* Fb = g_finb + (size_t)b * NN * DD;

    const int tid = threadIdx.x, lane = tid & 31, wid = tid >> 5;
    const int wm = (wid >> 1) << 5;
    const int wn = (wid & 1) << 6;

    float acc[2][8][4];
    #pragma unroll
    for (int i = 0; i < 2; i++)
        #pragma unroll
        for (int j = 0; j < 8; j++)
            #pragma unroll
            for (int k = 0; k < 4; k++) acc[i][j][k] = 0.f;

    const int er0 = tid & 127,         ec0 = (tid >> 7) << 3;
    const int er1 = (tid + 256) & 127, ec1 = ((tid + 256) >> 7) << 3;
    const int fk0 = tid >> 4,          fd0 = (tid & 15) << 3;
    const int fk1 = (tid + 256) >> 4,  fd1 = ((tid + 256) & 15) << 3;

    #define OUT_LOAD(kt, p)                                                           \
        do {                                                                          \
            cpa16(&Es[p][swA(er0, ec0)], Eb + (size_t)(row0 + er0) * NN + (kt) + ec0); \
            cpa16(&Es[p][swA(er1, ec1)], Eb + (size_t)(row0 + er1) * NN + (kt) + ec1); \
            cpa16(&Fs[p][swF(fk0, fd0)], Fb + (size_t)((kt) + fk0) * DD + col0 + fd0); \
            cpa16(&Fs[p][swF(fk1, fd1)], Fb + (size_t)((kt) + fk1) * DD + col0 + fd1); \
        } while (0)

    OUT_LOAD(0, 0);
    CP_COMMIT();

    for (int kti = 0; kti < KT_OUT; kti++) {
        const int p = kti & 1;
        if (kti + 1 < KT_OUT) {
            OUT_LOAD((kti + 1) * 32, p ^ 1);
            CP_COMMIT();
            CP_WAIT(1);
        } else {
            CP_WAIT(0);
        }
        __syncthreads();

        #pragma unroll
        for (int ks = 0; ks < 2; ks++) {
            uint32_t af[2][4];
            #pragma unroll
            for (int i = 0; i < 2; i++) {
                int row = wm + i * 16 + (lane & 15);
                int kh  = ks * 16 + ((lane >> 4) << 3);
                uint32_t ad = s2u(&Es[p][swA(row, kh)]);
                asm volatile("ldmatrix.sync.aligned.m8n8.x4.shared.b16 {%0,%1,%2,%3}, [%4];"
                    : "=r"(af[i][0]), "=r"(af[i][1]), "=r"(af[i][2]), "=r"(af[i][3])
                    : "r"(ad));
            }
            uint32_t bf[8][2];
            #pragma unroll
            for (int j2 = 0; j2 < 4; j2++) {
                int kr = ks * 16 + (lane & 7) + (((lane >> 3) & 1) << 3);
                int dh = wn + j2 * 16 + ((lane >> 4) << 3);
                uint32_t bd = s2u(&Fs[p][swF(kr, dh)]);
                asm volatile("ldmatrix.sync.aligned.m8n8.x4.trans.shared.b16 {%0,%1,%2,%3}, [%4];"
                    : "=r"(bf[j2 * 2][0]), "=r"(bf[j2 * 2][1]),
                      "=r"(bf[j2 * 2 + 1][0]), "=r"(bf[j2 * 2 + 1][1])
                    : "r"(bd));
            }
            #pragma unroll
            for (int i = 0; i < 2; i++)
                #pragma unroll
                for (int j = 0; j < 8; j++)
                    asm volatile(
                        "mma.sync.aligned.m16n8k16.row.col.f32.bf16.bf16.f32 "
                        "{%0,%1,%2,%3}, {%4,%5,%6,%7}, {%8,%9}, {%0,%1,%2,%3};"
                        : "+f"(acc[i][j][0]), "+f"(acc[i][j][1]),
                          "+f"(acc[i][j][2]), "+f"(acc[i][j][3])
                        : "r"(af[i][0]), "r"(af[i][1]), "r"(af[i][2]), "r"(af[i][3]),
                          "r"(bf[j][0]), "r"(bf[j][1]));
        }
        __syncthreads();
    }

    const float* F32 = fin + (size_t)b * NN * DD;
    float* O = out + (size_t)b * NN * DD;
    const int gr = lane >> 2, gc = (lane & 3) << 1;
    #pragma unroll
    for (int i = 0; i < 2; i++) {
        #pragma unroll
        for (int half = 0; half < 2; half++) {
            int r = row0 + wm + i * 16 + gr + half * 8;
            const float cw  = g_conf[b * NN + r];
            const float inv = g_rinv[b * NN + r];
            #pragma unroll
            for (int j = 0; j < 8; j++) {
                int c = col0 + wn + j * 8 + gc;
                float2 f = *(const float2*)(F32 + (size_t)r * DD + c);
                float2 o;
                o.x = cw * (acc[i][j][half * 2 + 0] * inv) + (1.0f - cw) * f.x;
                o.y = cw * (acc[i][j][half * 2 + 1] * inv) + (1.0f - cw) * f.y;
                *(float2*)(O + (size_t)r * DD + c) = o;
            }
        }
    }
}

// ---------------------------------------------------------------------------
extern "C" void kernel_launch(void* const* d_in, const int* in_sizes, int n_in,
                              void* d_out, int out_size) {
    const float* final_f = (const float*)d_in[0];
    const float* mid_f   = (const float*)d_in[1];
    float* out = (float*)d_out;

    static int configured = 0;
    if (!configured) {
        cudaFuncSetAttribute(sim_mma, cudaFuncAttributeMaxDynamicSharedMemorySize,
                             SIM_SMEM);
        configured = 1;
    }

    norm_kernel<<<BATCH * NN, 256>>>(mid_f);
    cvt_final<<<(int)(((size_t)BATCH * NN * DD / 4 + 255) / 256), 256>>>(
        (const float4*)final_f);

    sim_mma<<<dim3(NPAIRS, 1, BATCH), 256, SIM_SMEM>>>();

    rowsum_kernel<<<BATCH * NN, 128>>>();

    out_mma<<<dim3(DD / 128, NN / 128, BATCH), 256>>>(final_f, out);
}

// round 8
// speedup vs baseline: 5.0139x; 1.1199x over previous
#include <cuda_runtime.h>
#include <cuda_bf16.h>
#include <cuda_fp8.h>
#include <stdint.h>
#include <stddef.h>
#include <math.h>

#define BATCH 8
#define NN 2048
#define DD 768
#define NTILE 16
#define NPAIRS (NTILE * (NTILE + 1) / 2)   // 136 upper-triangle tiles

// ---------------- device scratch (allocation-free rule) ----------------
__device__ __nv_bfloat16 g_midn[(size_t)BATCH * NN * DD];   // normalized mid (bf16)
__device__ unsigned char g_ftp8[(size_t)BATCH * DD * NN];   // final^T (e4m3), [d][n]
__device__ unsigned char g_expb[(size_t)BATCH * NN * NN];   // e4m3 exp(sim), diag -> 1
__device__ unsigned      g_confbits[BATCH * NN];            // ordered-uint row max
__device__ float         g_conf[BATCH * NN];                // row max (confidence)
__device__ float         g_rinv[BATCH * NN];                // 1 / row sum of exp

__device__ __forceinline__ uint32_t s2u(const void* p) {
    return (uint32_t)__cvta_generic_to_shared(p);
}
__device__ __forceinline__ void cpa16(void* dst, const void* src) {
    asm volatile("cp.async.cg.shared.global [%0], [%1], 16;"
                 :: "r"(s2u(dst)), "l"(src));
}
#define CP_COMMIT() asm volatile("cp.async.commit_group;")
#define CP_WAIT(n)  asm volatile("cp.async.wait_group %0;" :: "n"(n))

// monotonic float<->uint for atomicMax
__device__ __forceinline__ unsigned fenc(float x) {
    unsigned b = __float_as_uint(x);
    return (b & 0x80000000u) ? ~b : (b | 0x80000000u);
}
__device__ __forceinline__ float fdec(unsigned e) {
    unsigned b = (e & 0x80000000u) ? (e ^ 0x80000000u) : ~e;
    return __uint_as_float(b);
}
// pack 2 floats -> e4m3x2 (16 bits)
__device__ __forceinline__ uint32_t pk2f8(float a, float b2) {
    return (uint32_t)__nv_cvt_float2_to_fp8x2(make_float2(a, b2),
                                              __NV_SATFINITE, __NV_E4M3);
}
__device__ __forceinline__ uint32_t pk4f8(float a, float b2, float c, float d) {
    return pk2f8(a, b2) | (pk2f8(c, d) << 16);
}
__device__ __forceinline__ float2 up2f8(uint16_t x) {
    __half2_raw hr = __nv_cvt_fp8x2_to_halfraw2((__nv_fp8x2_storage_t)x, __NV_E4M3);
    return __half22float2(*(__half2*)&hr);
}

// swizzled index (halves) for bf16 tiles with 32-half (64B) rows
__device__ __forceinline__ int swA(int row, int kh) {
    return (row << 5) | ((((kh >> 3) ^ ((row >> 1) & 3)) << 3));
}
// swizzled byte offset for fp8 tiles: 128 rows x 64 bytes, 16B chunks
__device__ __forceinline__ int off8(int r, int c16) {
    return (r << 6) | ((((c16) ^ ((r >> 1) & 3)) & 3) << 4);
}

// ---------------------------------------------------------------------------
// Kernel 1: L2-normalize mid along D -> bf16; reset g_confbits.
// ---------------------------------------------------------------------------
__global__ void norm_kernel(const float* __restrict__ mid) {
    const int row = blockIdx.x;
    if (threadIdx.x == 0) g_confbits[row] = fenc(-INFINITY);
    const float* x = mid + (size_t)row * DD;
    __nv_bfloat16* y = g_midn + (size_t)row * DD;

    float s = 0.f;
    for (int i = threadIdx.x; i < DD; i += blockDim.x) {
        float v = x[i];
        s += v * v;
    }
    __shared__ float sh[32];
    #pragma unroll
    for (int o = 16; o > 0; o >>= 1) s += __shfl_xor_sync(0xffffffffu, s, o);
    const int w = threadIdx.x >> 5, l = threadIdx.x & 31;
    if (l == 0) sh[w] = s;
    __syncthreads();
    if (w == 0) {
        float v = (threadIdx.x < (blockDim.x >> 5)) ? sh[threadIdx.x] : 0.f;
        #pragma unroll
        for (int o = 16; o > 0; o >>= 1) v += __shfl_xor_sync(0xffffffffu, v, o);
        if (threadIdx.x == 0) sh[0] = v;
    }
    __syncthreads();
    const float inv = 1.0f / fmaxf(sqrtf(sh[0]), 1e-12f);
    for (int i = threadIdx.x; i < DD; i += blockDim.x)
        y[i] = __float2bfloat16(x[i] * inv);
}

// ---------------------------------------------------------------------------
// Kernel 1b: transpose final fp32 [n][d] -> e4m3 [d][n].
// ---------------------------------------------------------------------------
__global__ void transpose_fp8(const float* __restrict__ fin) {
    __shared__ float t[32][33];
    const int b = blockIdx.z;
    const int d0 = blockIdx.x * 32, n0 = blockIdx.y * 32;
    const float* F = fin + (size_t)b * NN * DD;
    unsigned char* T = g_ftp8 + (size_t)b * DD * NN;
    const int x = threadIdx.x, y = threadIdx.y;
    #pragma unroll
    for (int i = 0; i < 4; i++)
        t[y + 8 * i][x] = F[(size_t)(n0 + y + 8 * i) * DD + d0 + x];
    __syncthreads();
    // thread (x,y): out row d0+x, bytes n0+y*4..+3
    uint32_t word = pk4f8(t[y * 4 + 0][x], t[y * 4 + 1][x],
                          t[y * 4 + 2][x], t[y * 4 + 3][x]);
    *(uint32_t*)(T + (size_t)(d0 + x) * NN + n0 + y * 4) = word;
}

// ---------------------------------------------------------------------------
// Kernel 2: sim GEMM (upper-triangle tiles, bf16 HMMA) -> exp(sim) e4m3
// + row-max atomics. SMEM-staged epilogue writes tile and transpose.
// ---------------------------------------------------------------------------
#define KT_SIM (DD / 32)
#define STG 4096
#define SIM_SMEM (128 * 129 * 4)

__global__ __launch_bounds__(256) void sim_mma() {
    extern __shared__ char dsm[];
    __nv_bfloat16* As = (__nv_bfloat16*)dsm;
    __nv_bfloat16* Bs = As + 2 * STG;
    float* T = (float*)dsm;

    int t = blockIdx.x, bi = 0, rem = NTILE;
    while (t >= rem) { t -= rem; rem--; bi++; }
    const int bj = bi + t;
    const int b = blockIdx.z;
    const int row0 = bi << 7, col0 = bj << 7;
    const bool diag = (bi == bj);
    const __nv_bfloat16* Ab = g_midn + (size_t)b * NN * DD;

    const int tid = threadIdx.x, lane = tid & 31, wid = tid >> 5;
    const int wm = (wid >> 1) << 5;
    const int wn = (wid & 1) << 6;

    float acc[2][8][4];
    #pragma unroll
    for (int i = 0; i < 2; i++)
        #pragma unroll
        for (int j = 0; j < 8; j++)
            #pragma unroll
            for (int k = 0; k < 4; k++) acc[i][j][k] = 0.f;

    const int r0q = tid & 127,          c0q = (tid >> 7) << 3;
    const int r1q = (tid + 256) & 127,  c1q = ((tid + 256) >> 7) << 3;

    #define SIM_LOAD(kt, p)                                                           \
        do {                                                                          \
            cpa16(&As[(p) * STG + swA(r0q, c0q)], Ab + (size_t)(row0 + r0q) * DD + (kt) + c0q); \
            cpa16(&As[(p) * STG + swA(r1q, c1q)], Ab + (size_t)(row0 + r1q) * DD + (kt) + c1q); \
            cpa16(&Bs[(p) * STG + swA(r0q, c0q)], Ab + (size_t)(col0 + r0q) * DD + (kt) + c0q); \
            cpa16(&Bs[(p) * STG + swA(r1q, c1q)], Ab + (size_t)(col0 + r1q) * DD + (kt) + c1q); \
        } while (0)

    SIM_LOAD(0, 0);
    CP_COMMIT();

    for (int kti = 0; kti < KT_SIM; kti++) {
        const int p = kti & 1;
        if (kti + 1 < KT_SIM) {
            SIM_LOAD((kti + 1) * 32, p ^ 1);
            CP_COMMIT();
            CP_WAIT(1);
        } else {
            CP_WAIT(0);
        }
        __syncthreads();

        #pragma unroll
        for (int ks = 0; ks < 2; ks++) {
            uint32_t af[2][4];
            #pragma unroll
            for (int i = 0; i < 2; i++) {
                int row = wm + i * 16 + (lane & 15);
                int kh  = ks * 16 + ((lane >> 4) << 3);
                uint32_t ad = s2u(&As[p * STG + swA(row, kh)]);
                asm volatile("ldmatrix.sync.aligned.m8n8.x4.shared.b16 {%0,%1,%2,%3}, [%4];"
                    : "=r"(af[i][0]), "=r"(af[i][1]), "=r"(af[i][2]), "=r"(af[i][3])
                    : "r"(ad));
            }
            uint32_t bf[8][2];
            #pragma unroll
            for (int j2 = 0; j2 < 4; j2++) {
                int row = wn + j2 * 16 + (lane & 7) + (((lane >> 4) & 1) << 3);
                int kh  = ks * 16 + (((lane >> 3) & 1) << 3);
                uint32_t bd = s2u(&Bs[p * STG + swA(row, kh)]);
                asm volatile("ldmatrix.sync.aligned.m8n8.x4.shared.b16 {%0,%1,%2,%3}, [%4];"
                    : "=r"(bf[j2 * 2][0]), "=r"(bf[j2 * 2][1]),
                      "=r"(bf[j2 * 2 + 1][0]), "=r"(bf[j2 * 2 + 1][1])
                    : "r"(bd));
            }
            #pragma unroll
            for (int i = 0; i < 2; i++)
                #pragma unroll
                for (int j = 0; j < 8; j++)
                    asm volatile(
                        "mma.sync.aligned.m16n8k16.row.col.f32.bf16.bf16.f32 "
                        "{%0,%1,%2,%3}, {%4,%5,%6,%7}, {%8,%9}, {%0,%1,%2,%3};"
                        : "+f"(acc[i][j][0]), "+f"(acc[i][j][1]),
                          "+f"(acc[i][j][2]), "+f"(acc[i][j][3])
                        : "r"(af[i][0]), "r"(af[i][1]), "r"(af[i][2]), "r"(af[i][3]),
                          "r"(bf[j][0]), "r"(bf[j][1]));
        }
        __syncthreads();
    }

    // ---- stage fp32 tile (diag zeroed) in SMEM ----
    const int gr = lane >> 2, gc = (lane & 3) << 1;
    #pragma unroll
    for (int i = 0; i < 2; i++) {
        const int rl = wm + i * 16 + gr;
        #pragma unroll
        for (int j = 0; j < 8; j++) {
            const int cl = wn + j * 8 + gc;
            const int gofs = (row0 + rl) - (col0 + cl);
            T[rl * 129 + cl]           = (gofs == 0)  ? 0.f : acc[i][j][0];
            T[rl * 129 + cl + 1]       = (gofs == 1)  ? 0.f : acc[i][j][1];
            T[(rl + 8) * 129 + cl]     = (gofs == -8) ? 0.f : acc[i][j][2];
            T[(rl + 8) * 129 + cl + 1] = (gofs == -7) ? 0.f : acc[i][j][3];
        }
    }
    __syncthreads();

    // ---- row pass: write exp(tile) as e4m3 + row-max atomics ----
    {
        const int rr = tid >> 1, cs = (tid & 1) << 6;
        float mx = -INFINITY;
        uint32_t* dst = (uint32_t*)(g_expb + (size_t)b * NN * NN
                                    + (size_t)(row0 + rr) * NN + col0 + cs);
        #pragma unroll
        for (int c = 0; c < 64; c += 4) {
            float v0 = T[rr * 129 + cs + c + 0];
            float v1 = T[rr * 129 + cs + c + 1];
            float v2 = T[rr * 129 + cs + c + 2];
            float v3 = T[rr * 129 + cs + c + 3];
            mx = fmaxf(mx, fmaxf(fmaxf(v0, v1), fmaxf(v2, v3)));
            dst[c >> 2] = pk4f8(__expf(v0), __expf(v1), __expf(v2), __expf(v3));
        }
        atomicMax(&g_confbits[b * NN + row0 + rr], fenc(mx));
    }

    // ---- col pass (mirror) for off-diagonal tiles ----
    if (!diag) {
        const int cc = tid >> 1, rs = (tid & 1) << 6;
        float mx = -INFINITY;
        uint32_t* dst = (uint32_t*)(g_expb + (size_t)b * NN * NN
                                    + (size_t)(col0 + cc) * NN + row0 + rs);
        #pragma unroll
        for (int r = 0; r < 64; r += 4) {
            float v0 = T[(rs + r + 0) * 129 + cc];
            float v1 = T[(rs + r + 1) * 129 + cc];
            float v2 = T[(rs + r + 2) * 129 + cc];
            float v3 = T[(rs + r + 3) * 129 + cc];
            mx = fmaxf(mx, fmaxf(fmaxf(v0, v1), fmaxf(v2, v3)));
            dst[r >> 2] = pk4f8(__expf(v0), __expf(v1), __expf(v2), __expf(v3));
        }
        atomicMax(&g_confbits[b * NN + col0 + cc], fenc(mx));
    }
}

// ---------------------------------------------------------------------------
// Kernel 3: row sums of e4m3 exp -> rinv; conf from confbits.
// ---------------------------------------------------------------------------
__global__ void rowsum_kernel() {
    const int row = blockIdx.x;
    const uint4* p = (const uint4*)(g_expb + (size_t)row * NN) + threadIdx.x;
    uint4 v = p[0];
    float s = 0.f;
    const uint32_t w4[4] = {v.x, v.y, v.z, v.w};
    #pragma unroll
    for (int h = 0; h < 4; h++) {
        float2 a = up2f8((uint16_t)(w4[h] & 0xFFFF));
        float2 b2 = up2f8((uint16_t)(w4[h] >> 16));
        s += (a.x + a.y) + (b2.x + b2.y);
    }
    __shared__ float sh[4];
    #pragma unroll
    for (int o = 16; o > 0; o >>= 1) s += __shfl_xor_sync(0xffffffffu, s, o);
    const int w = threadIdx.x >> 5, l = threadIdx.x & 31;
    if (l == 0) sh[w] = s;
    __syncthreads();
    if (threadIdx.x == 0) {
        float v2 = sh[0] + sh[1] + sh[2] + sh[3];
        g_conf[row] = fdec(g_confbits[row]);
        g_rinv[row] = 1.0f / v2;
    }
}

// ---------------------------------------------------------------------------
// Kernel 4: refined = (E @ F) * rinv ; out = cw*refined + (1-cw)*final.
// fp8 e4m3 QMMA m16n8k32. A = E [n][k] row-major, B = F^T [d][k] K-major.
// 128x128 tile, k-chunks of 64 bytes, cp.async 2-stage.
// ---------------------------------------------------------------------------
#define KT_OUT (NN / 64)

__global__ __launch_bounds__(256) void out_mma(const float* __restrict__ fin,
                                               float* __restrict__ out) {
    __shared__ unsigned char Es[2][128 * 64];
    __shared__ unsigned char Fs[2][128 * 64];
    const int b = blockIdx.z;
    const int row0 = blockIdx.y << 7;   // n rows
    const int col0 = blockIdx.x << 7;   // d cols
    const unsigned char* Eb = g_expb + (size_t)b * NN * NN;
    const unsigned char* Tb = g_ftp8 + (size_t)b * DD * NN;

    const int tid = threadIdx.x, lane = tid & 31, wid = tid >> 5;
    const int wm = (wid >> 1) << 5;
    const int wn = (wid & 1) << 6;

    float acc[2][8][4];
    #pragma unroll
    for (int i = 0; i < 2; i++)
        #pragma unroll
        for (int j = 0; j < 8; j++)
            #pragma unroll
            for (int k = 0; k < 4; k++) acc[i][j][k] = 0.f;

    // 512 16B chunks per tile; 2 per thread
    const int r0c = tid >> 2,          c0c = tid & 3;
    const int r1c = (tid + 256) >> 2,  c1c = (tid + 256) & 3;

    #define OUT_LOAD(kt, p)                                                           \
        do {                                                                          \
            cpa16(&Es[p][off8(r0c, c0c)], Eb + (size_t)(row0 + r0c) * NN + (kt) + c0c * 16); \
            cpa16(&Es[p][off8(r1c, c1c)], Eb + (size_t)(row0 + r1c) * NN + (kt) + c1c * 16); \
            cpa16(&Fs[p][off8(r0c, c0c)], Tb + (size_t)(col0 + r0c) * NN + (kt) + c0c * 16); \
            cpa16(&Fs[p][off8(r1c, c1c)], Tb + (size_t)(col0 + r1c) * NN + (kt) + c1c * 16); \
        } while (0)

    OUT_LOAD(0, 0);
    CP_COMMIT();

    for (int kti = 0; kti < KT_OUT; kti++) {
        const int p = kti & 1;
        if (kti + 1 < KT_OUT) {
            OUT_LOAD((kti + 1) * 64, p ^ 1);
            CP_COMMIT();
            CP_WAIT(1);
        } else {
            CP_WAIT(0);
        }
        __syncthreads();

        #pragma unroll
        for (int ks = 0; ks < 2; ks++) {
            uint32_t af[2][4];
            #pragma unroll
            for (int i = 0; i < 2; i++) {
                int row = wm + i * 16 + (lane & 15);
                int c16 = ks * 2 + (lane >> 4);
                uint32_t ad = s2u(&Es[p][off8(row, c16)]);
                asm volatile("ldmatrix.sync.aligned.m8n8.x4.shared.b16 {%0,%1,%2,%3}, [%4];"
                    : "=r"(af[i][0]), "=r"(af[i][1]), "=r"(af[i][2]), "=r"(af[i][3])
                    : "r"(ad));
            }
            uint32_t bf[8][2];
            #pragma unroll
            for (int j2 = 0; j2 < 4; j2++) {
                int row = wn + j2 * 16 + (lane & 7) + (((lane >> 4) & 1) << 3);
                int c16 = ks * 2 + ((lane >> 3) & 1);
                uint32_t bd = s2u(&Fs[p][off8(row, c16)]);
                asm volatile("ldmatrix.sync.aligned.m8n8.x4.shared.b16 {%0,%1,%2,%3}, [%4];"
                    : "=r"(bf[j2 * 2][0]), "=r"(bf[j2 * 2][1]),
                      "=r"(bf[j2 * 2 + 1][0]), "=r"(bf[j2 * 2 + 1][1])
                    : "r"(bd));
            }
            #pragma unroll
            for (int i = 0; i < 2; i++)
                #pragma unroll
                for (int j = 0; j < 8; j++)
                    asm volatile(
                        "mma.sync.aligned.m16n8k32.row.col.f32.e4m3.e4m3.f32 "
                        "{%0,%1,%2,%3}, {%4,%5,%6,%7}, {%8,%9}, {%0,%1,%2,%3};"
                        : "+f"(acc[i][j][0]), "+f"(acc[i][j][1]),
                          "+f"(acc[i][j][2]), "+f"(acc[i][j][3])
                        : "r"(af[i][0]), "r"(af[i][1]), "r"(af[i][2]), "r"(af[i][3]),
                          "r"(bf[j][0]), "r"(bf[j][1]));
        }
        __syncthreads();
    }

    const float* F32 = fin + (size_t)b * NN * DD;
    float* O = out + (size_t)b * NN * DD;
    const int gr = lane >> 2, gc = (lane & 3) << 1;
    #pragma unroll
    for (int i = 0; i < 2; i++) {
        #pragma unroll
        for (int half = 0; half < 2; half++) {
            int r = row0 + wm + i * 16 + gr + half * 8;
            const float cw  = g_conf[b * NN + r];
            const float inv = g_rinv[b * NN + r];
            #pragma unroll
            for (int j = 0; j < 8; j++) {
                int c = col0 + wn + j * 8 + gc;
                float2 f = *(const float2*)(F32 + (size_t)r * DD + c);
                float2 o;
                o.x = cw * (acc[i][j][half * 2 + 0] * inv) + (1.0f - cw) * f.x;
                o.y = cw * (acc[i][j][half * 2 + 1] * inv) + (1.0f - cw) * f.y;
                *(float2*)(O + (size_t)r * DD + c) = o;
            }
        }
    }
}

// ---------------------------------------------------------------------------
extern "C" void kernel_launch(void* const* d_in, const int* in_sizes, int n_in,
                              void* d_out, int out_size) {
    const float* final_f = (const float*)d_in[0];
    const float* mid_f   = (const float*)d_in[1];
    float* out = (float*)d_out;

    static int configured = 0;
    if (!configured) {
        cudaFuncSetAttribute(sim_mma, cudaFuncAttributeMaxDynamicSharedMemorySize,
                             SIM_SMEM);
        configured = 1;
    }

    norm_kernel<<<BATCH * NN, 256>>>(mid_f);
    transpose_fp8<<<dim3(DD / 32, NN / 32, BATCH), dim3(32, 8)>>>(final_f);

    sim_mma<<<dim3(NPAIRS, 1, BATCH), 256, SIM_SMEM>>>();

    rowsum_kernel<<<BATCH * NN, 128>>>();

    out_mma<<<dim3(DD / 128, NN / 128, BATCH), 256>>>(final_f, out);
}